// round 11
// baseline (speedup 1.0000x reference)
#include <cuda_runtime.h>
#include <cstdint>

// B=4096, T=1024, H=15
// Inputs: x[B*T], w_ih[15], w_hh[225], b_ih[15], b_hh[15], w_lin[15], b_lin[1]
// Output: out[B*T] float32
//
// 8 lanes per batch; lane li (0..7) owns hidden rows 2li and 2li+1.
// Lane 7's second row is the linear head (one step delayed).
// Per step: 4x LDS.128 broadcast + two 15-dots (3 accums) + MUFU.TANH
// + 1x STS.64 + 1 WARPSYNC. xp projections hoisted off the chain.

#define T_      1024
#define THREADS 64            // 2 warps = 8 groups (batches) per CTA
#define GROUPS  8
#define GRID    (4096 / GROUPS)   // 512 CTAs
#define HSTRIDE 20            // floats per group: 80B, 16B-aligned, conflict-free

__device__ __forceinline__ float tanha(float x) {
    float r; asm("tanh.approx.f32 %0, %1;" : "=f"(r) : "f"(x)); return r;
}

__global__ void __launch_bounds__(THREADS)
rnn_kernel(const float* __restrict__ x,
           const float* __restrict__ w_ih, const float* __restrict__ w_hh,
           const float* __restrict__ b_ih, const float* __restrict__ b_hh,
           const float* __restrict__ w_lin, const float* __restrict__ b_lin,
           float* __restrict__ out)
{
    __shared__ __align__(16) float hbuf[2][GROUPS][HSTRIDE];   // 1.25KB

    const int tid  = threadIdx.x;
    const int lane = tid & 31;
    const int li   = lane & 7;           // lane within group
    const int g    = tid >> 3;           // 0..7: batch within CTA
    const int b0   = blockIdx.x * GROUPS;
    const bool is_head = (li == 7);

    // Rows 2li and 2li+1. Lane 7: row 14 (regular) + head row (w_lin).
    const int r0 = 2 * li, r1 = 2 * li + 1;
    float w0[15], w1[15], wih0, wih1, bias0, bias1;
#pragma unroll
    for (int j = 0; j < 15; j++) w0[j] = w_hh[r0 * 15 + j];
    wih0  = w_ih[r0];
    bias0 = b_ih[r0] + b_hh[r0];
    if (!is_head) {
#pragma unroll
        for (int j = 0; j < 15; j++) w1[j] = w_hh[r1 * 15 + j];
        wih1  = w_ih[r1];
        bias1 = b_ih[r1] + b_hh[r1];
    } else {
#pragma unroll
        for (int j = 0; j < 15; j++) w1[j] = w_lin[j];
        wih1  = 0.0f;
        bias1 = b_lin[0];
    }

    // h0 = 0
    *reinterpret_cast<float2*>(&hbuf[0][g][2 * li]) = make_float2(0.f, 0.f);
    __syncwarp();

    const float* xrow = x   + (size_t)(b0 + g) * T_;
    float*       orow = out + (size_t)(b0 + g) * T_;
    float* const hb0 = &hbuf[0][g][0];
    float* const hb1 = &hbuf[1][g][0];

    float o0 = 0.f, o1 = 0.f, o2 = 0.f, o3 = 0.f;

    float4 xn = *reinterpret_cast<const float4*>(xrow);   // x[0..3]

#pragma unroll 1
    for (int m = 0; m < 256; ++m) {
        const float4 xc = xn;
        xn = *reinterpret_cast<const float4*>(xrow + (((m + 1) & 255) << 2));

        // Hoist the input projections for all 4 sub-steps (off the chain)
        float xp0[4], xp1[4];
        xp0[0] = fmaf(xc.x, wih0, bias0);  xp1[0] = fmaf(xc.x, wih1, bias1);
        xp0[1] = fmaf(xc.y, wih0, bias0);  xp1[1] = fmaf(xc.y, wih1, bias1);
        xp0[2] = fmaf(xc.z, wih0, bias0);  xp1[2] = fmaf(xc.z, wih1, bias1);
        xp0[3] = fmaf(xc.w, wih0, bias0);  xp1[3] = fmaf(xc.w, wih1, bias1);

#pragma unroll
        for (int u = 0; u < 4; ++u) {
            const float* hr = (u & 1) ? hb1 : hb0;
            float*       hw = (u & 1) ? hb0 : hb1;

            // Broadcast-load h: 4x LDS.128 (slot 15 junk, never used)
            float h[16];
            {
                float4 v0 = *reinterpret_cast<const float4*>(hr + 0);
                float4 v1 = *reinterpret_cast<const float4*>(hr + 4);
                float4 v2 = *reinterpret_cast<const float4*>(hr + 8);
                float4 v3 = *reinterpret_cast<const float4*>(hr + 12);
                h[0]=v0.x; h[1]=v0.y; h[2]=v0.z; h[3]=v0.w;
                h[4]=v1.x; h[5]=v1.y; h[6]=v1.z; h[7]=v1.w;
                h[8]=v2.x; h[9]=v2.y; h[10]=v2.z; h[11]=v2.w;
                h[12]=v3.x; h[13]=v3.y; h[14]=v3.z; h[15]=v3.w;
            }

            // Two 15-term dots (rows r0, r1), 3 accumulators each (depth 5)
            float a0 = fmaf(w0[0], h[0], xp0[u]);
            float a1 = w0[1] * h[1];
            float a2 = w0[2] * h[2];
            float c0 = fmaf(w1[0], h[0], xp1[u]);
            float c1 = w1[1] * h[1];
            float c2 = w1[2] * h[2];
#pragma unroll
            for (int j = 3; j < 15; j += 3) {
                a0 = fmaf(w0[j + 0], h[j + 0], a0);
                a1 = fmaf(w0[j + 1], h[j + 1], a1);
                a2 = fmaf(w0[j + 2], h[j + 2], a2);
                c0 = fmaf(w1[j + 0], h[j + 0], c0);
                c1 = fmaf(w1[j + 1], h[j + 1], c1);
                c2 = fmaf(w1[j + 2], h[j + 2], c2);
            }
            const float acc0 = a0 + (a1 + a2);
            const float acc1 = c0 + (c1 + c2);

            // Slot 15 (lane7's second slot) is never read -> no SEL needed.
            *reinterpret_cast<float2*>(hw + 2 * li) =
                make_float2(tanha(acc0), tanha(acc1));

            // Head schedule: lane7's acc1 at step t=4m+u equals out[t-1]
            if (u == 0) {
                o3 = acc1;
                if (m > 0 && is_head)
                    *reinterpret_cast<float4*>(orow + ((m - 1) << 2)) =
                        make_float4(o0, o1, o2, o3);
            } else if (u == 1) { o0 = acc1; }
            else if (u == 2)   { o1 = acc1; }
            else               { o2 = acc1; }
            __syncwarp();
        }
    }

    // Epilogue: out[1023] from final h (in hb0), flush out[1020..1023]
    if (is_head) {
        float c0 = bias1, c1 = 0.f, c2 = 0.f;
#pragma unroll
        for (int j = 0; j < 15; j += 3) {
            c0 = fmaf(w1[j + 0], hb0[j + 0], c0);
            c1 = fmaf(w1[j + 1], hb0[j + 1], c1);
            c2 = fmaf(w1[j + 2], hb0[j + 2], c2);
        }
        o3 = c0 + (c1 + c2);
        *reinterpret_cast<float4*>(orow + (T_ - 4)) = make_float4(o0, o1, o2, o3);
    }
}

extern "C" void kernel_launch(void* const* d_in, const int* in_sizes, int n_in,
                              void* d_out, int out_size)
{
    const float* x     = (const float*)d_in[0];
    const float* w_ih  = (const float*)d_in[1];
    const float* w_hh  = (const float*)d_in[2];
    const float* b_ih  = (const float*)d_in[3];
    const float* b_hh  = (const float*)d_in[4];
    const float* w_lin = (const float*)d_in[5];
    const float* b_lin = (const float*)d_in[6];
    float* out = (float*)d_out;
    rnn_kernel<<<GRID, THREADS>>>(x, w_ih, w_hh, b_ih, b_hh, w_lin, b_lin, out);
}